// round 17
// baseline (speedup 1.0000x reference)
#include <cuda_runtime.h>
#include <cuda_bf16.h>
#include <cuda_fp16.h>
#include <math.h>
#include <stdint.h>

#define NB 256
#define TT 64
#define HH 1024
#define GG 4096
#define LL 16
#define KP 2048   // fp16 2-term split folded into K

__device__ __forceinline__ uint32_t smem_u32(const void* p) {
    uint32_t a;
    asm("{ .reg .u64 t; cvta.to.shared.u64 t, %1; cvt.u32.u64 %0, t; }" : "=r"(a) : "l"(p));
    return a;
}
#define CP16(dst, src) asm volatile("cp.async.cg.shared.global [%0], [%1], 16;" :: "r"(dst), "l"(src) : "memory")
#define CP_COMMIT() asm volatile("cp.async.commit_group;" ::: "memory")
#define CP_WAIT1() asm volatile("cp.async.wait_group 1;" ::: "memory")
#define LDSM4(r0, r1, r2, r3, addr) \
    asm volatile("ldmatrix.sync.aligned.m8n8.x4.shared.b16 {%0,%1,%2,%3}, [%4];" \
        : "=r"(r0), "=r"(r1), "=r"(r2), "=r"(r3) : "r"(addr))
#define MMA16816(d, a, b) \
    asm volatile("mma.sync.aligned.m16n8k16.row.col.f32.f16.f16.f32 " \
        "{%0,%1,%2,%3}, {%4,%5,%6,%7}, {%8,%9}, {%0,%1,%2,%3};" \
        : "+f"((d)[0]), "+f"((d)[1]), "+f"((d)[2]), "+f"((d)[3]) \
        : "r"((a)[0]), "r"((a)[1]), "r"((a)[2]), "r"((a)[3]), "r"((b)[0]), "r"((b)[1]))

// ------------------------------------------------ scratch
__device__ float g_XW[(size_t)NB * TT * GG];      // permuted cols, fp32
__device__ __half g_Ph[(size_t)NB * LL * GG];     // permuted cols, fp16
__device__ float g_AT[(size_t)NB * LL * HH];      // fp32 for scores
__device__ float g_w[NB * LL];                    // softmax weights
__device__ float g_h[NB * HH];
__device__ float g_c[NB * HH];
__device__ float g_bperm[GG];
__device__ __half g_xs[(size_t)NB * TT * KP];     // [xhi|xlo]
__device__ __half g_ATs[(size_t)NB * LL * KP];    // [hi|lo]
__device__ __half g_Wxs[(size_t)GG * KP];         // [Whi|Whi] (B side)
__device__ __half g_Whs[(size_t)GG * KP];
__device__ __half g_Was[(size_t)GG * KP];
__device__ __half g_hsA[(size_t)NB * KP];         // h ping [hi|lo]
__device__ __half g_hsB[(size_t)NB * KP];         // h pong

// ------------------------------------------------ prep kernels
__global__ void x_split_kernel(const float* __restrict__ x) {
    size_t gid = (size_t)blockIdx.x * 256 + threadIdx.x;  // float4 id
    size_t r = gid >> 8;
    int kq = (int)(gid & 255);
    float4 v = ((const float4*)x)[gid];
    __half2 h0 = __floats2half2_rn(v.x, v.y);
    __half2 h1 = __floats2half2_rn(v.z, v.w);
    float2 f0 = __half22float2(h0), f1 = __half22float2(h1);
    __half2 l0 = __floats2half2_rn(v.x - f0.x, v.y - f0.y);
    __half2 l1 = __floats2half2_rn(v.z - f1.x, v.w - f1.y);
    __half2* base = (__half2*)(g_xs + r * KP);
    base[kq * 2] = h0;        base[kq * 2 + 1] = h1;
    base[512 + kq * 2] = l0;  base[512 + kq * 2 + 1] = l1;
}

__global__ void at_prep_kernel(const float* __restrict__ A) {
    int idx = blockIdx.x * 256 + threadIdx.x;  // n*1024 + h
    int n = idx >> 10, h = idx & 1023;
    const float4* a4 = (const float4*)(A + (size_t)idx * 16);
    float s = 0.f;
#pragma unroll
    for (int q = 0; q < 4; q++) {
        float4 v = a4[q];
        float vv[4] = {v.x, v.y, v.z, v.w};
#pragma unroll
        for (int e = 0; e < 4; e++) {
            int l = q * 4 + e;
            float val = vv[e];
            g_AT[((size_t)n * LL + l) * HH + h] = val;
            __half hi = __float2half_rn(val);
            __half lo = __float2half_rn(val - __half2float(hi));
            size_t o = ((size_t)n * LL + l) * KP + h;
            g_ATs[o] = hi; g_ATs[o + 1024] = lo;
            s += val;
        }
    }
    float h0 = s * (1.0f / 16.0f);
    g_h[idx] = h0;
    g_c[idx] = h0;
    __half hh = __float2half_rn(h0);
    __half hl = __float2half_rn(h0 - __half2float(hh));
    size_t o = (size_t)n * KP + h;
    g_hsA[o] = hh; g_hsA[o + 1024] = hl;
}

// transpose + fp16 + permute: col c = g*1024+u -> rp = ((u>>3)<<5)|(g<<3)|(u&7)
__global__ void wsplit_kernel(const float* __restrict__ W, __half* __restrict__ Ws) {
    __shared__ float tile[32][33];
    int c0 = blockIdx.x * 32, k0 = blockIdx.y * 32;
    int tx = threadIdx.x;
    for (int i = threadIdx.y; i < 32; i += 8)
        tile[i][tx] = W[(size_t)(k0 + i) * GG + c0 + tx];
    __syncthreads();
    for (int i = threadIdx.y; i < 32; i += 8) {
        int c = c0 + i;
        int u = c & 1023, g = c >> 10;
        int rp = ((u >> 3) << 5) | (g << 3) | (u & 7);
        __half hi = __float2half_rn(tile[tx][i]);
        size_t o = (size_t)rp * KP + k0 + tx;
        Ws[o] = hi; Ws[o + 1024] = hi;
    }
}

__global__ void bias_perm_kernel(const float* __restrict__ b) {
    int idx = blockIdx.x * 256 + threadIdx.x;   // permuted col
    int g = (idx >> 3) & 3;
    int u = (idx & 7) | ((idx >> 5) << 3);
    g_bperm[idx] = b[g * 1024 + u];
}

// ------------------------------------------------ mma.sync fp16 GEMM, K'=2048
// EPI: 0 plain fp32, 1 +bias fp32, 2 fused combine+LSTM gates, 3 fp16 store
template <int BM, int BN, int WARPS_M, int WARPS_N, int EPI>
__global__ void __launch_bounds__(WARPS_M * WARPS_N * 32)
gemm_mma(const __half* __restrict__ Ag, const __half* __restrict__ Bg,
         float* __restrict__ Cout, const float* __restrict__ addv,
         __half* __restrict__ hnext, float* __restrict__ out, int t)
{
    constexpr int NTH = WARPS_M * WARPS_N * 32;
    constexpr int WM = BM / WARPS_M, WN = BN / WARPS_N;
    constexpr int MT = WM / 16, NT2 = WN / 8;
    constexpr int KC = KP / 64;
    constexpr int ABUF = BM * 128, BBUF = BN * 128;

    extern __shared__ char smem[];
    const uint32_t sA = smem_u32(smem);
    const uint32_t sB = sA + 2 * ABUF;
    const int tid = threadIdx.x, lane = tid & 31, warp = tid >> 5;
    const int wm0 = (warp / WARPS_N) * WM, wn0 = (warp % WARPS_N) * WN;
    const int m0 = blockIdx.y * BM, n0 = blockIdx.x * BN;
    const __half* Abase = Ag + (size_t)m0 * KP;
    const __half* Bbase = Bg + (size_t)n0 * KP;

    float acc[MT][NT2][4];
#pragma unroll
    for (int i = 0; i < MT; i++)
#pragma unroll
        for (int j = 0; j < NT2; j++)
#pragma unroll
            for (int e = 0; e < 4; e++) acc[i][j][e] = 0.f;

#define ISSUE1(kc, buf) do { \
    const __half* As_ = Abase + (kc) * 64; \
    _Pragma("unroll") \
    for (int i = 0; i < BM * 8 / NTH; i++) { \
        int idx = tid + i * NTH, r = idx >> 3, q = idx & 7; \
        CP16(sA + (buf) * ABUF + r * 128 + (((q ^ (r & 7)) << 4)), As_ + (size_t)r * KP + q * 8); \
    } \
    const __half* Bs_ = Bbase + (kc) * 64; \
    _Pragma("unroll") \
    for (int i = 0; i < BN * 8 / NTH; i++) { \
        int idx = tid + i * NTH, r = idx >> 3, q = idx & 7; \
        CP16(sB + (buf) * BBUF + r * 128 + (((q ^ (r & 7)) << 4)), Bs_ + (size_t)r * KP + q * 8); \
    } \
} while (0)

    ISSUE1(0, 0); CP_COMMIT();
    ISSUE1(1, 1); CP_COMMIT();

    for (int kc = 0; kc < KC; kc++) {
        CP_WAIT1();
        __syncthreads();
        const int buf = kc & 1;
        const uint32_t a0b = sA + buf * ABUF, b0b = sB + buf * BBUF;
#pragma unroll
        for (int ks = 0; ks < 4; ks++) {
            uint32_t af[MT][4], bf[NT2][2];
#pragma unroll
            for (int mt = 0; mt < MT; mt++) {
                int r = wm0 + mt * 16 + (lane & 15);
                int q = ks * 2 + (lane >> 4);
                LDSM4(af[mt][0], af[mt][1], af[mt][2], af[mt][3],
                      a0b + r * 128 + (((q ^ (r & 7)) << 4)));
            }
#pragma unroll
            for (int p = 0; p < NT2 / 2; p++) {
                int n = wn0 + p * 16 + (lane & 7) + ((lane >> 4) << 3);
                int q = ks * 2 + ((lane >> 3) & 1);
                LDSM4(bf[2 * p][0], bf[2 * p][1], bf[2 * p + 1][0], bf[2 * p + 1][1],
                      b0b + n * 128 + (((q ^ (n & 7)) << 4)));
            }
#pragma unroll
            for (int mt = 0; mt < MT; mt++)
#pragma unroll
                for (int nt = 0; nt < NT2; nt++)
                    MMA16816(acc[mt][nt], af[mt], bf[nt]);
        }
        __syncthreads();
        if (kc + 2 < KC) ISSUE1(kc + 2, buf);
        CP_COMMIT();
    }
#undef ISSUE1

    const int l4 = lane >> 2, q2 = (lane & 3) * 2;
    if (EPI == 0 || EPI == 1) {
#pragma unroll
        for (int mt = 0; mt < MT; mt++) {
            int r0 = m0 + wm0 + mt * 16 + l4;
#pragma unroll
            for (int nt = 0; nt < NT2; nt++) {
                int col = n0 + wn0 + nt * 8 + q2;
                float bx = 0.f, by = 0.f;
                if (EPI == 1) { bx = addv[col]; by = addv[col + 1]; }
                *(float2*)(Cout + (size_t)r0 * GG + col) =
                    make_float2(acc[mt][nt][0] + bx, acc[mt][nt][1] + by);
                *(float2*)(Cout + (size_t)(r0 + 8) * GG + col) =
                    make_float2(acc[mt][nt][2] + bx, acc[mt][nt][3] + by);
            }
        }
    } else if (EPI == 3) {
        __half* Ch = (__half*)Cout;
#pragma unroll
        for (int mt = 0; mt < MT; mt++) {
            int r0 = m0 + wm0 + mt * 16 + l4;
#pragma unroll
            for (int nt = 0; nt < NT2; nt++) {
                int col = n0 + wn0 + nt * 8 + q2;
                *(__half2*)(Ch + (size_t)r0 * GG + col) =
                    __floats2half2_rn(acc[mt][nt][0], acc[mt][nt][1]);
                *(__half2*)(Ch + (size_t)(r0 + 8) * GG + col) =
                    __floats2half2_rn(acc[mt][nt][2], acc[mt][nt][3]);
            }
        }
    } else {
        // ---- fused combine (z = XW_t + sum_l w_l P_l) + LSTM gates ----
        // smem double-buffers are dead now; reuse: zs[BM*BN] fp32, ws[BM*LL] fp32
        float* zs = (float*)smem;                 // BM*BN*4 = 32KB
        float* ws = zs + BM * BN;                 // BM*LL*4 = 8KB
        __syncthreads();                          // all mainloop smem reads done
        for (int i = tid; i < BM * LL; i += NTH)
            ws[i] = g_w[(m0 + (i >> 4)) * LL + (i & 15)];
        __syncthreads();
#pragma unroll
        for (int i = tid; i < BM * BN / 4; i += NTH) {
            int r = i >> 4, cq = i & 15;          // BN/4 = 16 float4 per row
            int row = m0 + r;
            float4 a = *(const float4*)(addv + ((size_t)row * TT + t) * GG + n0 + cq * 4);
            const __half* pb = g_Ph + (size_t)row * LL * GG + n0 + cq * 4;
            const float* wr = ws + r * LL;
#pragma unroll
            for (int l = 0; l < LL; l++) {
                uint2 pv = *(const uint2*)(pb + (size_t)l * GG);
                float2 f0 = __half22float2(*(__half2*)&pv.x);
                float2 f1 = __half22float2(*(__half2*)&pv.y);
                float w = wr[l];
                a.x += w * f0.x; a.y += w * f0.y; a.z += w * f1.x; a.w += w * f1.y;
            }
            *(float4*)(zs + r * BN + cq * 4) = a;
        }
        __syncthreads();

        const int U0 = (((n0 + wn0) >> 5) << 3) + q2;
#pragma unroll
        for (int mt = 0; mt < MT; mt++) {
#pragma unroll
            for (int rs = 0; rs < 2; rs++) {
                int rloc = wm0 + mt * 16 + l4 + rs * 8;
                int row = m0 + rloc;
                const float* zr = zs + rloc * BN + wn0 + q2;
#pragma unroll
                for (int us = 0; us < 2; us++) {
                    float ai = acc[mt][0][rs * 2 + us] + zr[us];
                    float afv = acc[mt][1][rs * 2 + us] + zr[8 + us];
                    float ao = acc[mt][2][rs * 2 + us] + zr[16 + us];
                    float ag = acc[mt][3][rs * 2 + us] + zr[24 + us];
                    int u = U0 + us;
                    float gi = 1.f / (1.f + expf(-ai));
                    float gf = 1.f / (1.f + expf(-afv));
                    float go = 1.f / (1.f + expf(-ao));
                    float gg = tanhf(ag);
                    size_t hx = (size_t)row * HH + u;
                    float cn = gf * g_c[hx] + gi * gg;
                    g_c[hx] = cn;
                    float hn = go * tanhf(cn);
                    g_h[hx] = hn;
                    __half hh = __float2half_rn(hn);
                    __half hl = __float2half_rn(hn - __half2float(hh));
                    size_t hb = (size_t)row * KP + u;
                    hnext[hb] = hh; hnext[hb + 1024] = hl;
                    out[((size_t)row * TT + t) * HH + u] = hn;
                }
            }
        }
    }
}

// ------------------------------------------------ scores + softmax -> g_w
__global__ __launch_bounds__(512) void scores_kernel() {
    __shared__ float sw[16];
    const int n = blockIdx.x;
    const int tid = threadIdx.x, warp = tid >> 5, lane = tid & 31;
    {
        const float* hp = g_h + (size_t)n * HH;
        const float* ap = g_AT + ((size_t)n * LL + warp) * HH;
        float acc = 0.f;
        for (int k = lane; k < HH; k += 32) acc += hp[k] * ap[k];
#pragma unroll
        for (int o = 16; o > 0; o >>= 1) acc += __shfl_xor_sync(0xffffffffu, acc, o);
        if (lane == 0) sw[warp] = acc * 0.03125f;
    }
    __syncthreads();
    if (warp == 0) {
        float s = (lane < 16) ? sw[lane] : -1e30f;
        float m = s;
#pragma unroll
        for (int o = 16; o > 0; o >>= 1) m = fmaxf(m, __shfl_xor_sync(0xffffffffu, m, o));
        float e = (lane < 16) ? expf(s - m) : 0.f;
        float tot = e;
#pragma unroll
        for (int o = 16; o > 0; o >>= 1) tot += __shfl_xor_sync(0xffffffffu, tot, o);
        if (lane < 16) g_w[n * LL + lane] = e / tot;
    }
}

// ------------------------------------------------ launch
extern "C" void kernel_launch(void* const* d_in, const int* in_sizes, int n_in,
                              void* d_out, int out_size) {
    const float* x = (const float*)d_in[0];
    const float* A = (const float*)d_in[1];
    const float* Wx = (const float*)d_in[2];
    const float* Wh = (const float*)d_in[3];
    const float* Wattn = (const float*)d_in[4];
    const float* b = (const float*)d_in[5];
    float* out = (float*)d_out;

    float *p_xw, *p_bp;
    __half *p_ph, *p_xs, *p_ats, *p_wxs, *p_whs, *p_was, *p_hsA, *p_hsB;
    cudaGetSymbolAddress((void**)&p_xw, g_XW);
    cudaGetSymbolAddress((void**)&p_ph, g_Ph);
    cudaGetSymbolAddress((void**)&p_bp, g_bperm);
    cudaGetSymbolAddress((void**)&p_xs, g_xs);
    cudaGetSymbolAddress((void**)&p_ats, g_ATs);
    cudaGetSymbolAddress((void**)&p_wxs, g_Wxs);
    cudaGetSymbolAddress((void**)&p_whs, g_Whs);
    cudaGetSymbolAddress((void**)&p_was, g_Was);
    cudaGetSymbolAddress((void**)&p_hsA, g_hsA);
    cudaGetSymbolAddress((void**)&p_hsB, g_hsB);

    constexpr int SM_P1 = 2 * (128 + 128) * 128;  // 65536
    constexpr int SM_ST = 2 * (128 + 64) * 128;   // 49152 (>= 40KB epilogue reuse)
    cudaFuncSetAttribute((const void*)gemm_mma<128, 128, 2, 4, 1>,
                         cudaFuncAttributeMaxDynamicSharedMemorySize, SM_P1);
    cudaFuncSetAttribute((const void*)gemm_mma<128, 128, 2, 4, 3>,
                         cudaFuncAttributeMaxDynamicSharedMemorySize, SM_P1);
    cudaFuncSetAttribute((const void*)gemm_mma<128, 64, 4, 2, 2>,
                         cudaFuncAttributeMaxDynamicSharedMemorySize, SM_ST);

    // prep
    x_split_kernel<<<(NB * TT * HH / 4) / 256, 256>>>(x);
    at_prep_kernel<<<(NB * HH) / 256, 256>>>(A);
    {
        dim3 g(GG / 32, HH / 32), blk(32, 8);
        wsplit_kernel<<<g, blk>>>(Wx, p_wxs);
        wsplit_kernel<<<g, blk>>>(Wh, p_whs);
        wsplit_kernel<<<g, blk>>>(Wattn, p_was);
    }
    bias_perm_kernel<<<GG / 256, 256>>>(b);

    // phase 1: XW = x' @ Wx'^T + b ; P = AT' @ Wa'^T (fp16 store)
    {
        dim3 g(GG / 128, (NB * TT) / 128);
        gemm_mma<128, 128, 2, 4, 1><<<g, 256, SM_P1>>>(p_xs, p_wxs, p_xw, p_bp, nullptr, nullptr, 0);
    }
    {
        dim3 g(GG / 128, (NB * LL) / 128);
        gemm_mma<128, 128, 2, 4, 3><<<g, 256, SM_P1>>>(p_ats, p_was, (float*)p_ph, nullptr, nullptr, nullptr, 0);
    }

    // phase 2: sequential scan, 2 launches per step (scores, then gemm+combine+gates)
    for (int t = 0; t < TT; t++) {
        scores_kernel<<<NB, 512>>>();
        __half* hc = (t & 1) ? p_hsB : p_hsA;
        __half* hn = (t & 1) ? p_hsA : p_hsB;
        dim3 g(GG / 64, NB / 128);
        gemm_mma<128, 64, 4, 2, 2><<<g, 256, SM_ST>>>(hc, p_whs, nullptr, p_xw, hn, out, t);
    }
}